// round 14
// baseline (speedup 1.0000x reference)
#include <cuda_runtime.h>

#define N_NODES 50000
#define N_EDGES 800000
#define DIM     128
#define NELEM   (N_NODES * DIM)          /* 6,400,000 */

/* ---------------- scratch (device globals; no allocation allowed) --------- */
__device__ float g_deg[N_NODES];              /* degree, then dinv            */
__device__ int   g_cnt[N_NODES];              /* per-node in-degree count     */
__device__ int   g_off[N_NODES + 1];          /* CSR offsets (exclusive scan) */
__device__ int   g_cur[N_NODES];              /* scatter cursors              */
__device__ int   g_bsum[256];                 /* scan block sums              */
__device__ int   g_srow[N_EDGES];             /* CSR: source row per edge     */
__device__ float g_snorm[N_EDGES];            /* CSR: normalized weight       */
__device__ float g_H[NELEM];                  /* GEMM output per layer        */
__device__ float g_A[NELEM];                  /* layer-1 result               */
__device__ int   g_is64;                      /* edge_index dtype flag        */

__device__ __forceinline__ int edge_at(const void* ei, int is64, int idx) {
    if (is64) return (int)((const long long*)ei)[idx];
    return ((const int*)ei)[idx];
}

/* ---------------- init (+ dtype sniff, warp-parallel) --------------------- *
 * Node ids are in [0,50000) -> < 2^31, nonnegative. If the buffer is int64
 * little-endian every odd 32-bit word is 0; if int32 the odds are random
 * node ids (64 of them all zero: p ~ (2e-5)^64).                            */
__global__ void k_init(const int* __restrict__ ei) {
    int i = blockIdx.x * 256 + threadIdx.x;
    if (i < N_NODES) { g_deg[i] = 2.0f; g_cnt[i] = 0; }   /* self-loop w=2 */
    if (blockIdx.x == 0 && threadIdx.x < 32) {
        int v = ei[threadIdx.x * 2 + 1] | ei[threadIdx.x * 2 + 65];
        int any = __reduce_or_sync(0xffffffffu, v);
        if (threadIdx.x == 0) g_is64 = (any == 0) ? 1 : 0;
    }
}

/* ---------------- degree + count ------------------------------------------ */
__global__ void k_count(const void* ei, const float* __restrict__ ew) {
    int e = blockIdx.x * 512 + threadIdx.x;
    if (e >= N_EDGES) return;
    int c = edge_at(ei, g_is64, N_EDGES + e);
    atomicAdd(&g_deg[c], ew[e]);
    atomicAdd(&g_cnt[c], 1);
}

/* ---------------- exclusive scan of g_cnt (3 kernels) + dinv -------------- */
#define SCAN_BLOCKS 196   /* 196*256 = 50176 >= 50000 */

__global__ void k_scan_block() {
    __shared__ int s[256];
    int t = threadIdx.x;
    int i = blockIdx.x * 256 + t;
    /* fused: deg -> dinv (independent of the scan below) */
    if (i < N_NODES) {
        float d = g_deg[i];
        g_deg[i] = (d > 0.f) ? rsqrtf(d) : 0.f;
    }
    int v = (i < N_NODES) ? g_cnt[i] : 0;
    s[t] = v; __syncthreads();
    #pragma unroll
    for (int d = 1; d < 256; d <<= 1) {
        int x = 0;
        if (t >= d) x = s[t - d];
        __syncthreads();
        if (t >= d) s[t] += x;
        __syncthreads();
    }
    if (i < N_NODES) g_off[i] = s[t] - v;          /* exclusive */
    if (t == 255) g_bsum[blockIdx.x] = s[255];
}

__global__ void k_scan_top() {
    __shared__ int s[256];
    int t = threadIdx.x;
    int v = (t < SCAN_BLOCKS) ? g_bsum[t] : 0;
    s[t] = v; __syncthreads();
    #pragma unroll
    for (int d = 1; d < 256; d <<= 1) {
        int x = 0;
        if (t >= d) x = s[t - d];
        __syncthreads();
        if (t >= d) s[t] += x;
        __syncthreads();
    }
    if (t < SCAN_BLOCKS) g_bsum[t] = s[t] - v;     /* exclusive */
    if (t == 0) g_off[N_NODES] = N_EDGES;          /* sentinel  */
}

__global__ void k_scan_add() {
    int i = blockIdx.x * 256 + threadIdx.x;
    if (i < N_NODES) {
        int o = g_off[i] + g_bsum[blockIdx.x];
        g_off[i] = o;
        g_cur[i] = o;
    }
}

/* ---------------- permute edges into CSR + compute norm ------------------- */
__global__ void k_permute(const void* ei, const float* __restrict__ ew) {
    int e = blockIdx.x * 512 + threadIdx.x;
    if (e >= N_EDGES) return;
    int is64 = g_is64;
    int r = edge_at(ei, is64, e);
    int c = edge_at(ei, is64, N_EDGES + e);
    float w = g_deg[r] * ew[e] * g_deg[c];
    int pos = atomicAdd(&g_cur[c], 1);
    g_srow[pos] = r;
    g_snorm[pos] = w;
}

/* ---------------- GEMM: H = X @ W  (fp32, fma.rn.f32x2) ------------------- */
#define TILE_ROWS 128
#define XS_STRIDE 132
#define GEMM_SMEM ((DIM * DIM + DIM * XS_STRIDE) * 4)

__global__ void __launch_bounds__(256, 1)
k_gemm(const float* __restrict__ X, const float* __restrict__ W,
       float* __restrict__ Hout) {
    extern __shared__ float smem[];
    float* ws = smem;                 /* W[k][j], 128x128                    */
    float* xs = smem + DIM * DIM;     /* X^T[k][r], stride 132               */
    const int t = threadIdx.x;
    const int rowBase = blockIdx.x * TILE_ROWS;

    {
        const float4* Wv = (const float4*)W;
        float4* wsv = (float4*)ws;
        #pragma unroll
        for (int i = t; i < DIM * DIM / 4; i += 256) wsv[i] = Wv[i];
    }
    for (int idx = t; idx < TILE_ROWS * DIM / 4; idx += 256) {
        int r  = idx >> 5;
        int k4 = (idx & 31) << 2;
        int row = rowBase + r;
        float4 v = make_float4(0.f, 0.f, 0.f, 0.f);
        if (row < N_NODES) v = *(const float4*)(X + (size_t)row * DIM + k4);
        xs[(k4 + 0) * XS_STRIDE + r] = v.x;
        xs[(k4 + 1) * XS_STRIDE + r] = v.y;
        xs[(k4 + 2) * XS_STRIDE + r] = v.z;
        xs[(k4 + 3) * XS_STRIDE + r] = v.w;
    }
    __syncthreads();

    const int j0 = (t >> 4) * 8;
    const int r0 = (t & 15) * 8;

    unsigned long long acc[8][4];
    #pragma unroll
    for (int a = 0; a < 8; a++)
        #pragma unroll
        for (int b = 0; b < 4; b++) acc[a][b] = 0ull;

    union F4U2 { float4 f4; unsigned long long u2[2]; };

    #pragma unroll 8
    for (int k = 0; k < DIM; k++) {
        float4 xa = *(const float4*)(xs + k * XS_STRIDE + r0);
        float4 xb = *(const float4*)(xs + k * XS_STRIDE + r0 + 4);
        F4U2 wa, wb;
        wa.f4 = *(const float4*)(ws + k * DIM + j0);
        wb.f4 = *(const float4*)(ws + k * DIM + j0 + 4);
        float xr[8] = {xa.x, xa.y, xa.z, xa.w, xb.x, xb.y, xb.z, xb.w};
        #pragma unroll
        for (int r = 0; r < 8; r++) {
            unsigned long long xx;
            asm("mov.b64 %0, {%1, %1};" : "=l"(xx) : "f"(xr[r]));
            asm("fma.rn.f32x2 %0, %1, %2, %0;" : "+l"(acc[r][0]) : "l"(xx), "l"(wa.u2[0]));
            asm("fma.rn.f32x2 %0, %1, %2, %0;" : "+l"(acc[r][1]) : "l"(xx), "l"(wa.u2[1]));
            asm("fma.rn.f32x2 %0, %1, %2, %0;" : "+l"(acc[r][2]) : "l"(xx), "l"(wb.u2[0]));
            asm("fma.rn.f32x2 %0, %1, %2, %0;" : "+l"(acc[r][3]) : "l"(xx), "l"(wb.u2[1]));
        }
    }

    #pragma unroll
    for (int r = 0; r < 8; r++) {
        int row = rowBase + r0 + r;
        if (row >= N_NODES) continue;
        float o[8];
        #pragma unroll
        for (int p = 0; p < 4; p++)
            asm("mov.b64 {%0, %1}, %2;" : "=f"(o[2 * p]), "=f"(o[2 * p + 1]) : "l"(acc[r][p]));
        *(float4*)(Hout + (size_t)row * DIM + j0)     = make_float4(o[0], o[1], o[2], o[3]);
        *(float4*)(Hout + (size_t)row * DIM + j0 + 4) = make_float4(o[4], o[5], o[6], o[7]);
    }
}

/* ---------------- JAX threefry2x32, key (0,42) ----------------------------
 * PARTITIONABLE layout (default since jax 0.4.36, Dec 2024):
 * counts = iota(uint64, size); per element n:
 *   (o0,o1) = threefry2x32(key=(0,42); x0 = n>>32 = 0, x1 = lo32(n) = n)
 *   bits    = o0 ^ o1                                   (32-bit output)
 * bernoulli keep <=> uniform < 0.5 <=> bits < 2^31 <=> top bit clear.
 * (Fallback if bench shows rel_err ~O(1): original split-halves layout.)   */
__device__ __forceinline__ unsigned int dropout_bits(unsigned int n) {
    const unsigned int ks0 = 0u, ks1 = 42u;
    const unsigned int ks2 = ks0 ^ ks1 ^ 0x1BD11BDAu;
    unsigned int ks[3] = {ks0, ks1, ks2};
    const int R[2][4] = {{13, 15, 26, 6}, {17, 29, 16, 24}};
    unsigned int x0 = 0u + ks0;      /* counter hi = 0                      */
    unsigned int x1 = n  + ks1;      /* counter lo = linear index           */
    #pragma unroll
    for (int i = 0; i < 5; i++) {
        #pragma unroll
        for (int j = 0; j < 4; j++) {
            x0 += x1;
            x1 = __funnelshift_l(x1, x1, R[i & 1][j]);
            x1 ^= x0;
        }
        x0 += ks[(i + 1) % 3];
        x1 += ks[(i + 2) % 3] + (unsigned int)(i + 1);
    }
    return x0 ^ x1;
}

/* ---------------- aggregation: warp per destination node ------------------ *
 * acc = 2*dinv[c]^2 * H[c]  +  sum_{e in CSR[c]} norm[e] * H[row[e]]
 * LAYER 1 epilogue: A = relu(acc + b1)
 * LAYER 2 epilogue: out = dropout(relu(acc + b2))
 * Unroll-4 gathers -> MLP=4 against L2 latency. 512-thr blocks (16 warps). */
template <int LAYER>
__global__ void __launch_bounds__(512)
k_agg(const float* __restrict__ H, float* __restrict__ out,
      const float* __restrict__ bias) {
    int c = (blockIdx.x * 512 + threadIdx.x) >> 5;
    int lane = threadIdx.x & 31;
    if (c >= N_NODES) return;

    const float4* Hv = (const float4*)H;
    float dinv = g_deg[c];
    float sw = 2.0f * dinv * dinv;
    float4 h = Hv[(size_t)c * 32 + lane];
    float4 a0 = make_float4(sw * h.x, sw * h.y, sw * h.z, sw * h.w);
    float4 a1 = make_float4(0.f, 0.f, 0.f, 0.f);

    int j = g_off[c];
    const int end = g_off[c + 1];
    for (; j + 3 < end; j += 4) {
        int   r0 = g_srow[j],      r1 = g_srow[j + 1];
        int   r2 = g_srow[j + 2],  r3 = g_srow[j + 3];
        float w0 = g_snorm[j],     w1 = g_snorm[j + 1];
        float w2 = g_snorm[j + 2], w3 = g_snorm[j + 3];
        float4 v0 = Hv[(size_t)r0 * 32 + lane];
        float4 v1 = Hv[(size_t)r1 * 32 + lane];
        float4 v2 = Hv[(size_t)r2 * 32 + lane];
        float4 v3 = Hv[(size_t)r3 * 32 + lane];
        a0.x += w0 * v0.x; a0.y += w0 * v0.y; a0.z += w0 * v0.z; a0.w += w0 * v0.w;
        a1.x += w1 * v1.x; a1.y += w1 * v1.y; a1.z += w1 * v1.z; a1.w += w1 * v1.w;
        a0.x += w2 * v2.x; a0.y += w2 * v2.y; a0.z += w2 * v2.z; a0.w += w2 * v2.w;
        a1.x += w3 * v3.x; a1.y += w3 * v3.y; a1.z += w3 * v3.z; a1.w += w3 * v3.w;
    }
    for (; j < end; j++) {
        int r0 = g_srow[j];
        float w0 = g_snorm[j];
        float4 v0 = Hv[(size_t)r0 * 32 + lane];
        a0.x += w0 * v0.x; a0.y += w0 * v0.y; a0.z += w0 * v0.z; a0.w += w0 * v0.w;
    }
    a0.x += a1.x; a0.y += a1.y; a0.z += a1.z; a0.w += a1.w;

    float4 bv = ((const float4*)bias)[lane];
    a0.x = fmaxf(a0.x + bv.x, 0.f);
    a0.y = fmaxf(a0.y + bv.y, 0.f);
    a0.z = fmaxf(a0.z + bv.z, 0.f);
    a0.w = fmaxf(a0.w + bv.w, 0.f);

    if (LAYER == 2) {
        unsigned int n = (unsigned int)c * DIM + (unsigned int)(lane * 4);
        a0.x = (dropout_bits(n + 0) >> 31) ? 0.f : a0.x * 2.0f;
        a0.y = (dropout_bits(n + 1) >> 31) ? 0.f : a0.y * 2.0f;
        a0.z = (dropout_bits(n + 2) >> 31) ? 0.f : a0.z * 2.0f;
        a0.w = (dropout_bits(n + 3) >> 31) ? 0.f : a0.w * 2.0f;
    }
    ((float4*)out)[(size_t)c * 32 + lane] = a0;
}

/* ---------------- launch --------------------------------------------------- */
extern "C" void kernel_launch(void* const* d_in, const int* in_sizes, int n_in,
                              void* d_out, int out_size) {
    const float* x  = (const float*)d_in[0];
    const void*  ei = d_in[1];
    const float* ew = (const float*)d_in[2];
    const float* W1 = (const float*)d_in[3];
    const float* b1 = (const float*)d_in[4];
    const float* W2 = (const float*)d_in[5];
    const float* b2 = (const float*)d_in[6];
    float* out = (float*)d_out;

    float *pH, *pA;
    cudaGetSymbolAddress((void**)&pH, g_H);
    cudaGetSymbolAddress((void**)&pA, g_A);

    cudaFuncSetAttribute(k_gemm, cudaFuncAttributeMaxDynamicSharedMemorySize, GEMM_SMEM);

    const int edgeBlocks = (N_EDGES + 511) / 512;                 /* 1563  */
    const int gemmBlocks = (N_NODES + TILE_ROWS - 1) / TILE_ROWS; /* 391   */
    const int aggBlocks  = (N_NODES * 32 + 511) / 512;            /* 3125  */

    k_init<<<SCAN_BLOCKS, 256>>>((const int*)ei);
    k_count<<<edgeBlocks, 512>>>(ei, ew);
    k_scan_block<<<SCAN_BLOCKS, 256>>>();
    k_scan_top<<<1, 256>>>();
    k_scan_add<<<SCAN_BLOCKS, 256>>>();
    k_permute<<<edgeBlocks, 512>>>(ei, ew);

    /* layer 1 */
    k_gemm<<<gemmBlocks, 256, GEMM_SMEM>>>(x, W1, pH);
    k_agg<1><<<aggBlocks, 512>>>(pH, pA, b1);

    /* layer 2 */
    k_gemm<<<gemmBlocks, 256, GEMM_SMEM>>>(pA, W2, pH);
    k_agg<2><<<aggBlocks, 512>>>(pH, out, b2);
}